// round 13
// baseline (speedup 1.0000x reference)
#include <cuda_runtime.h>
#include <cuda_bf16.h>
#include <cstdint>

// ---------------------------------------------------------------------------
// Problem constants
// ---------------------------------------------------------------------------
#define BB        4
#define LL        5000
#define HH        256
#define WW        256
#define HW        (HH * WW)          // 65536
#define C_IN      256
#define DIM_LOI   128
#define N_PTS0    32
#define N_PTS1    8
#define DIM_FC    1024
#define N_OUT     2500
#define NROWS     (BB * LL)          // 20000
#define NPAD      20096              // 157 * 128

// ---------------------------------------------------------------------------
// Static scratch (no allocations allowed)
// ---------------------------------------------------------------------------
__device__ float g_x[(size_t)BB * HW * DIM_LOI];      // fc1 out, pixel-major [b][hw][c]
__device__ float g_feat[(size_t)NPAD * DIM_FC];       // pooled features (pad rows stay 0)
__device__ float g_h1[(size_t)NPAD * DIM_FC];
__device__ float g_h2[(size_t)NPAD * DIM_FC];
__device__ float g_wfc1T[(size_t)C_IN * DIM_LOI];     // fc1_w transposed [k][n]
__device__ float g_s[(size_t)NROWS * 4];              // softmax scores
__device__ int   g_key[NROWS];
__device__ int   g_order[BB * LL];
__device__ int   g_cnt[BB];

// ---------------------------------------------------------------------------
// helpers
// ---------------------------------------------------------------------------
__device__ __forceinline__ uint32_t smem_u32(const void* p) {
    uint32_t a;
    asm("{ .reg .u64 t; cvta.to.shared.u64 t, %1; cvt.u32.u64 %0, t; }" : "=r"(a) : "l"(p));
    return a;
}
__device__ __forceinline__ void ldsm4(uint32_t r[4], uint32_t addr) {
    asm volatile("ldmatrix.sync.aligned.m8n8.x4.shared.b16 {%0,%1,%2,%3}, [%4];"
                 : "=r"(r[0]), "=r"(r[1]), "=r"(r[2]), "=r"(r[3]) : "r"(addr));
}
__device__ __forceinline__ void mma_bf16(float* c, const uint32_t* a, const uint32_t* b) {
    asm volatile(
        "mma.sync.aligned.m16n8k16.row.col.f32.bf16.bf16.f32 "
        "{%0,%1,%2,%3}, {%4,%5,%6,%7}, {%8,%9}, {%0,%1,%2,%3};"
        : "+f"(c[0]), "+f"(c[1]), "+f"(c[2]), "+f"(c[3])
        : "r"(a[0]), "r"(a[1]), "r"(a[2]), "r"(a[3]), "r"(b[0]), "r"(b[1]));
}
__device__ __forceinline__ void split_bf(float v, uint32_t& h, uint32_t& l) {
    __nv_bfloat16 hb = __float2bfloat16_rn(v);
    float r = v - __bfloat162float(hb);
    __nv_bfloat16 lb = __float2bfloat16_rn(r);
    h = (uint32_t)*(uint16_t*)&hb;
    l = (uint32_t)*(uint16_t*)&lb;
}
__device__ __forceinline__ uint32_t bpack(uint32_t lo16, uint32_t hi16) {
    return lo16 | (hi16 << 16);
}

// ---------------------------------------------------------------------------
// bf16 smem geometry, K-chunk = 32:
//   A: 128 rows x 32 bf16, 80B row stride (conflict-free LDSM: row offsets
//      mod 128 all distinct). B: 16 packed-pair rows [k/2][n] u32, 136-u32
//      row stride.
// ---------------------------------------------------------------------------
#define KCH   32
#define AROWB 80
#define ST_AB (128 * AROWB)             // 10240 B
#define BSTRU 136
#define ST_BB (16 * BSTRU * 4)          // 8704 B
#define STAGE_B (2 * ST_AB + 2 * ST_BB) // 37888 B
#define SMEM_GEMM (2 * STAGE_B)         // 75776 B
// stage layout: Ah @0, Al @ST_AB, Bh @2*ST_AB, Bl @2*ST_AB+ST_BB

// bf16 LDSM lane offset (bytes), within a k16 half
__device__ __forceinline__ int ldsm_lane_off_bf(int lane) {
    int row = (((lane >> 3) & 1) << 3) + (lane & 7);
    int colB = (lane >> 4) << 4;
    return row * AROWB + colB;
}

// ---------------------------------------------------------------------------
// 3xBF16 compute on a converted 128x32 stage: two k16 halves,
// per warp: 16 ldsm + 32 LDS + 96 MMA.
// ---------------------------------------------------------------------------
__device__ __forceinline__ void compute_stage_bf(
    uint32_t AhU, uint32_t AlU,
    const uint32_t* __restrict__ Bhp, const uint32_t* __restrict__ Blp,
    int warp_n, int gr, int tg, float acc[4][4][4])
{
#pragma unroll
    for (int h = 0; h < 2; h++) {
        uint32_t bh[4][2], bl[4][2];
#pragma unroll
        for (int nt = 0; nt < 4; nt++) {
            int c = warp_n + nt * 8 + gr;
            bh[nt][0] = Bhp[(8 * h + tg) * BSTRU + c];
            bh[nt][1] = Bhp[(8 * h + tg + 4) * BSTRU + c];
            bl[nt][0] = Blp[(8 * h + tg) * BSTRU + c];
            bl[nt][1] = Blp[(8 * h + tg + 4) * BSTRU + c];
        }
#pragma unroll
        for (int mt = 0; mt < 4; mt++) {
            uint32_t ah[4], al[4];
            const uint32_t off = (uint32_t)(mt * 16 * AROWB + h * 32);
            ldsm4(ah, AhU + off);
            ldsm4(al, AlU + off);
#pragma unroll
            for (int nt = 0; nt < 4; nt++) {
                mma_bf16(acc[mt][nt], ah, bh[nt]);
                mma_bf16(acc[mt][nt], ah, bl[nt]);
                mma_bf16(acc[mt][nt], al, bh[nt]);
            }
        }
    }
}

// pack a float4 pair-of-k rows into hi/lo uint4 (B path)
__device__ __forceinline__ void pack_b_pair(float4 rA, float4 rB,
                                            uint4& hv, uint4& lv)
{
    uint32_t ha, la, hb, lb;
    split_bf(rA.x, ha, la); split_bf(rB.x, hb, lb);
    hv.x = bpack(ha, hb); lv.x = bpack(la, lb);
    split_bf(rA.y, ha, la); split_bf(rB.y, hb, lb);
    hv.y = bpack(ha, hb); lv.y = bpack(la, lb);
    split_bf(rA.z, ha, la); split_bf(rB.z, hb, lb);
    hv.z = bpack(ha, hb); lv.z = bpack(la, lb);
    split_bf(rA.w, ha, la); split_bf(rB.w, hb, lb);
    hv.w = bpack(ha, hb); lv.w = bpack(la, lb);
}

// ---------------------------------------------------------------------------
// MLP GEMM (3xBF16, K-chunk 32): C = relu(A[M,1024] @ W[1024,1024] + bias)
// Block tile 128x128, 256 thr, double-buffered, 2 CTAs/SM. 32 chunks.
// ---------------------------------------------------------------------------
__global__ __launch_bounds__(256, 2)
void gemm_mma3(const float* __restrict__ A, const float* __restrict__ W,
               const float* __restrict__ bias, float* __restrict__ C)
{
    extern __shared__ __align__(16) char sm[];

    const int tid  = threadIdx.x;
    const int lane = tid & 31;
    const int wid  = tid >> 5;
    const int m0   = blockIdx.y * 128;
    const int n0   = blockIdx.x * 128;
    const int warp_m = (wid & 1) * 64;
    const int warp_n = (wid >> 1) * 32;
    const int gr = lane >> 2;
    const int tg = lane & 3;
    const uint32_t AU0 = smem_u32(sm)
        + (uint32_t)(warp_m * AROWB + ldsm_lane_off_bf(lane));

    float acc[4][4][4];
#pragma unroll
    for (int mt = 0; mt < 4; mt++)
#pragma unroll
        for (int nt = 0; nt < 4; nt++)
#pragma unroll
            for (int r = 0; r < 4; r++) acc[mt][nt][r] = 0.f;

    // A: 128 rows x 8 float4 = 1024 f4; thread -> rows a_r+32q (q=0..3), col a_j
    const int a_r = tid >> 3;            // 0..31
    const int a_j = tid & 7;             // 0..7
    // B: 16 pair-rows x 32 f4-pairs; thread -> pairs b_p, b_p+8; n4 cols
    const int b_p  = tid >> 5;           // 0..7
    const int b_n4 = (tid & 31) << 2;

    const float* Abase = A + (size_t)(m0 + a_r) * 1024 + a_j * 4;
    const float* Bbase = W + n0 + b_n4;

    float4 ra[4];
    float4 rbA[2], rbB[2];

    auto load_chunk = [&](int ch) {
        const size_t ko = (size_t)ch * KCH;
#pragma unroll
        for (int q = 0; q < 4; q++)
            ra[q] = *(const float4*)(Abase + (size_t)(32 * q) * 1024 + ko);
#pragma unroll
        for (int i = 0; i < 2; i++) {
            const size_t k0 = ko + 2 * (b_p + 8 * i);
            rbA[i] = *(const float4*)(Bbase + k0 * 1024);
            rbB[i] = *(const float4*)(Bbase + (k0 + 1) * 1024);
        }
    };
    auto store_chunk = [&](int p) {
        char* st = sm + p * STAGE_B;
#pragma unroll
        for (int q = 0; q < 4; q++) {
            uint32_t h0, l0, h1, l1, h2, l2, h3, l3;
            split_bf(ra[q].x, h0, l0); split_bf(ra[q].y, h1, l1);
            split_bf(ra[q].z, h2, l2); split_bf(ra[q].w, h3, l3);
            uint2 hv = make_uint2(bpack(h0, h1), bpack(h2, h3));
            uint2 lv = make_uint2(bpack(l0, l1), bpack(l2, l3));
            int off = (a_r + 32 * q) * AROWB + a_j * 8;
            *(uint2*)(st + off) = hv;
            *(uint2*)(st + ST_AB + off) = lv;
        }
#pragma unroll
        for (int i = 0; i < 2; i++) {
            uint4 hv, lv;
            pack_b_pair(rbA[i], rbB[i], hv, lv);
            int off = ((b_p + 8 * i) * BSTRU + b_n4) * 4;
            *(uint4*)(st + 2 * ST_AB + off) = hv;
            *(uint4*)(st + 2 * ST_AB + ST_BB + off) = lv;
        }
    };
    auto compute_chunk = [&](int p) {
        const char* st = sm + p * STAGE_B;
        compute_stage_bf(AU0 + (uint32_t)(p * STAGE_B),
                         AU0 + (uint32_t)(p * STAGE_B + ST_AB),
                         (const uint32_t*)(st + 2 * ST_AB),
                         (const uint32_t*)(st + 2 * ST_AB + ST_BB),
                         warp_n, gr, tg, acc);
    };

    load_chunk(0);
    store_chunk(0);
    __syncthreads();

    for (int ch = 1; ch <= 32; ch++) {
        if (ch < 32) load_chunk(ch);
        compute_chunk((ch - 1) & 1);
        if (ch < 32) store_chunk(ch & 1);
        __syncthreads();
    }

    // ---- epilogue: bias + relu
#pragma unroll
    for (int mt = 0; mt < 4; mt++) {
        int row = m0 + warp_m + mt * 16 + gr;
#pragma unroll
        for (int nt = 0; nt < 4; nt++) {
            int col = n0 + warp_n + nt * 8 + tg * 2;
            float b0 = bias[col], b1 = bias[col + 1];
            float2 v0, v1;
            v0.x = fmaxf(acc[mt][nt][0] + b0, 0.f);
            v0.y = fmaxf(acc[mt][nt][1] + b1, 0.f);
            v1.x = fmaxf(acc[mt][nt][2] + b0, 0.f);
            v1.y = fmaxf(acc[mt][nt][3] + b1, 0.f);
            *(float2*)(C + (size_t)row * 1024 + col) = v0;
            *(float2*)(C + (size_t)(row + 8) * 1024 + col) = v1;
        }
    }
}

// ---------------------------------------------------------------------------
// fc1 GEMM (3xBF16, K-chunk 32): x[b][hw][o] = feature . fc1_w^T + fc1_b
// A K-major gather (16 scalar LDG/thread); B = g_wfc1T [k][128]. 8 chunks.
// ---------------------------------------------------------------------------
__global__ __launch_bounds__(256, 2)
void gemm_fc1(const float* __restrict__ feature, const float* __restrict__ Wt,
              const float* __restrict__ bias, float* __restrict__ X)
{
    extern __shared__ __align__(16) char sm[];

    const int tid  = threadIdx.x;
    const int lane = tid & 31;
    const int wid  = tid >> 5;
    const int b    = blockIdx.z;
    const int m0   = blockIdx.y * 128;
    const int warp_m = (wid & 1) * 64;
    const int warp_n = (wid >> 1) * 32;
    const int gr = lane >> 2;
    const int tg = lane & 3;
    const uint32_t AU0 = smem_u32(sm)
        + (uint32_t)(warp_m * AROWB + ldsm_lane_off_bf(lane));

    const float* Ab = feature + (size_t)b * C_IN * HW;
    float* Cb = X + (size_t)b * HW * DIM_LOI;

    float acc[4][4][4];
#pragma unroll
    for (int mt = 0; mt < 4; mt++)
#pragma unroll
        for (int nt = 0; nt < 4; nt++)
#pragma unroll
            for (int r = 0; r < 4; r++) acc[mt][nt][r] = 0.f;

    // A: thread -> m = tid&127, k half a_kh (0 or 16), 16 scalar coalesced LDGs
    const int a_m  = tid & 127;
    const int a_kh = (tid >> 7) << 4;
    // B: thread -> pairs b_p, b_p+8; n4 cols
    const int b_p  = tid >> 5;
    const int b_n4 = (tid & 31) << 2;

    const float* Acol = Ab + (size_t)a_kh * HW + m0 + a_m;
    const float* Bbase = Wt + b_n4;

    float ra[16];
    float4 rbA[2], rbB[2];

    auto load_chunk = [&](int ch) {
        const size_t ko = (size_t)ch * KCH;
#pragma unroll
        for (int j = 0; j < 16; j++)
            ra[j] = Acol[(ko + j) * HW];
#pragma unroll
        for (int i = 0; i < 2; i++) {
            const size_t k0 = ko + 2 * (b_p + 8 * i);
            rbA[i] = *(const float4*)(Bbase + k0 * 128);
            rbB[i] = *(const float4*)(Bbase + (k0 + 1) * 128);
        }
    };
    auto store_chunk = [&](int p) {
        char* st = sm + p * STAGE_B;
        {
            uint32_t h[16], l[16];
#pragma unroll
            for (int j = 0; j < 16; j++) split_bf(ra[j], h[j], l[j]);
            int off = a_m * AROWB + a_kh * 2;
            uint4 hv0 = make_uint4(bpack(h[0], h[1]), bpack(h[2], h[3]),
                                   bpack(h[4], h[5]), bpack(h[6], h[7]));
            uint4 hv1 = make_uint4(bpack(h[8], h[9]), bpack(h[10], h[11]),
                                   bpack(h[12], h[13]), bpack(h[14], h[15]));
            uint4 lv0 = make_uint4(bpack(l[0], l[1]), bpack(l[2], l[3]),
                                   bpack(l[4], l[5]), bpack(l[6], l[7]));
            uint4 lv1 = make_uint4(bpack(l[8], l[9]), bpack(l[10], l[11]),
                                   bpack(l[12], l[13]), bpack(l[14], l[15]));
            *(uint4*)(st + off) = hv0;
            *(uint4*)(st + off + 16) = hv1;
            *(uint4*)(st + ST_AB + off) = lv0;
            *(uint4*)(st + ST_AB + off + 16) = lv1;
        }
#pragma unroll
        for (int i = 0; i < 2; i++) {
            uint4 hv, lv;
            pack_b_pair(rbA[i], rbB[i], hv, lv);
            int off = ((b_p + 8 * i) * BSTRU + b_n4) * 4;
            *(uint4*)(st + 2 * ST_AB + off) = hv;
            *(uint4*)(st + 2 * ST_AB + ST_BB + off) = lv;
        }
    };
    auto compute_chunk = [&](int p) {
        const char* st = sm + p * STAGE_B;
        compute_stage_bf(AU0 + (uint32_t)(p * STAGE_B),
                         AU0 + (uint32_t)(p * STAGE_B + ST_AB),
                         (const uint32_t*)(st + 2 * ST_AB),
                         (const uint32_t*)(st + 2 * ST_AB + ST_BB),
                         warp_n, gr, tg, acc);
    };

    load_chunk(0);
    store_chunk(0);
    __syncthreads();

    for (int ch = 1; ch <= 8; ch++) {
        if (ch < 8) load_chunk(ch);
        compute_chunk((ch - 1) & 1);
        if (ch < 8) store_chunk(ch & 1);
        __syncthreads();
    }

#pragma unroll
    for (int mt = 0; mt < 4; mt++) {
        int row = m0 + warp_m + mt * 16 + gr;
#pragma unroll
        for (int nt = 0; nt < 4; nt++) {
            int col = warp_n + nt * 8 + tg * 2;
            float b0 = bias[col], b1 = bias[col + 1];
            float2 v0, v1;
            v0.x = acc[mt][nt][0] + b0;
            v0.y = acc[mt][nt][1] + b1;
            v1.x = acc[mt][nt][2] + b0;
            v1.y = acc[mt][nt][3] + b1;
            *(float2*)(Cb + (size_t)row * 128 + col) = v0;
            *(float2*)(Cb + (size_t)(row + 8) * 128 + col) = v1;
        }
    }
}

// ---------------------------------------------------------------------------
// fc1_w [128][256] -> Wt [256][128]
// ---------------------------------------------------------------------------
__global__ __launch_bounds__(256)
void transpose_fc1(const float* __restrict__ s, float* __restrict__ d)
{
    __shared__ float t[32][33];
    const int bx = blockIdx.x * 32;   // k
    const int by = blockIdx.y * 32;   // n
    const int tx = threadIdx.x, ty = threadIdx.y;
#pragma unroll
    for (int r = 0; r < 32; r += 8)
        t[ty + r][tx] = s[(size_t)(by + ty + r) * 256 + bx + tx];
    __syncthreads();
#pragma unroll
    for (int r = 0; r < 32; r += 8)
        d[(size_t)(bx + ty + r) * 128 + by + tx] = t[tx][ty + r];
}

// ---------------------------------------------------------------------------
// Bilinear sampling + maxpool. One block per line, thread = channel.
// ---------------------------------------------------------------------------
__global__ __launch_bounds__(128)
void sample_kernel(const float* __restrict__ lines, float* __restrict__ feat)
{
    const int bl = blockIdx.x;
    const int b  = bl / LL;
    const int c  = threadIdx.x;

    const float* xb = g_x + (size_t)b * HW * DIM_LOI;

    float4 ln = *(const float4*)(lines + (size_t)bl * 4);
    const float x0 = ln.x, y0 = ln.y, x1 = ln.z, y1 = ln.w;

    __shared__ float stage[DIM_LOI * N_PTS1];

    float maxv = 0.f;
#pragma unroll 4
    for (int pt = 0; pt < N_PTS0; pt++) {
        float lam = (float)pt * (1.0f / 31.0f);
        float px = x0 * lam + x1 * (1.0f - lam) - 0.5f;
        float py = y0 * lam + y1 * (1.0f - lam) - 0.5f;

        float px0 = fminf(fmaxf(floorf(px), 0.f), (float)(HH - 1));
        float py0 = fminf(fmaxf(floorf(py), 0.f), (float)(WW - 1));
        float px1 = fminf(px0 + 1.f, (float)(HH - 1));
        float py1 = fminf(py0 + 1.f, (float)(WW - 1));
        int ix0 = (int)px0, iy0 = (int)py0, ix1 = (int)px1, iy1 = (int)py1;

        float w00 = (px1 - px) * (py1 - py);
        float w10 = (px - px0) * (py1 - py);
        float w01 = (px1 - px) * (py - py0);
        float w11 = (px - px0) * (py - py0);

        const float* t00 = xb + (size_t)(ix0 * WW + iy0) * DIM_LOI + c;
        const float* t10 = xb + (size_t)(ix1 * WW + iy0) * DIM_LOI + c;
        const float* t01 = xb + (size_t)(ix0 * WW + iy1) * DIM_LOI + c;
        const float* t11 = xb + (size_t)(ix1 * WW + iy1) * DIM_LOI + c;
        float v = w00 * (*t00) + w10 * (*t10) + w01 * (*t01) + w11 * (*t11);

        if ((pt & 3) == 0) maxv = v; else maxv = fmaxf(maxv, v);
        if ((pt & 3) == 3) stage[c * N_PTS1 + (pt >> 2)] = maxv;
    }
    __syncthreads();

    float* frow = feat + (size_t)bl * DIM_FC;
    for (int i = c; i < DIM_FC; i += DIM_LOI) frow[i] = stage[i];
}

// ---------------------------------------------------------------------------
// Final layer (1024 -> 4) + softmax + keep/key.
// ---------------------------------------------------------------------------
__global__ __launch_bounds__(128)
void layer3_kernel(const float* __restrict__ h2, const float* __restrict__ w3,
                   const float* __restrict__ b3)
{
    const int row = blockIdx.x;
    const int tid = threadIdx.x;
    const float* hr = h2 + (size_t)row * DIM_FC;

    float acc[4] = {0.f, 0.f, 0.f, 0.f};
    for (int k = tid; k < DIM_FC; k += 128) {
        float hv = hr[k];
        float4 wv = *(const float4*)(w3 + (size_t)k * 4);
        acc[0] += hv * wv.x; acc[1] += hv * wv.y;
        acc[2] += hv * wv.z; acc[3] += hv * wv.w;
    }
#pragma unroll
    for (int off = 16; off; off >>= 1)
#pragma unroll
        for (int n = 0; n < 4; n++)
            acc[n] += __shfl_down_sync(0xffffffffu, acc[n], off);

    __shared__ float red[4][4];
    if ((tid & 31) == 0)
#pragma unroll
        for (int n = 0; n < 4; n++) red[tid >> 5][n] = acc[n];
    __syncthreads();

    if (tid == 0) {
        float lg[4];
#pragma unroll
        for (int n = 0; n < 4; n++)
            lg[n] = red[0][n] + red[1][n] + red[2][n] + red[3][n] + b3[n];
        float mx = fmaxf(fmaxf(lg[0], lg[1]), fmaxf(lg[2], lg[3]));
        float e[4], sum = 0.f;
#pragma unroll
        for (int n = 0; n < 4; n++) { e[n] = __expf(lg[n] - mx); sum += e[n]; }
        float inv = 1.0f / sum;
        float s0 = e[0] * inv, s1 = e[1] * inv, s2 = e[2] * inv, s3 = e[3] * inv;
        float4 sv = {s0, s1, s2, s3};
        *(float4*)(g_s + (size_t)row * 4) = sv;

        bool keep = ((s1 > 0.25f) || (s2 > 0.25f) || (s3 > 0.25f)) && (s0 < 0.25f);
        int am = 0; float best = s0;
        if (s1 > best) { best = s1; am = 1; }
        if (s2 > best) { best = s2; am = 2; }
        if (s3 > best) { best = s3; am = 3; }
        g_key[row] = keep ? am : -1;
    }
}

// ---------------------------------------------------------------------------
// Stable counting sort by key desc (buckets 3,2,1). One block per batch.
// ---------------------------------------------------------------------------
__global__ __launch_bounds__(1024)
void select_kernel()
{
    const int b = blockIdx.x;
    const int t = threadIdx.x;
    const int* key = g_key + b * LL;

    __shared__ int sc[3][1024];

    const int l0 = t * 5;
    const int l1 = min(l0 + 5, LL);
    int n1 = 0, n2 = 0, n3 = 0;
    for (int i = l0; i < l1; i++) {
        int k = key[i];
        n1 += (k == 1); n2 += (k == 2); n3 += (k == 3);
    }
    sc[0][t] = n1; sc[1][t] = n2; sc[2][t] = n3;
    __syncthreads();

    for (int off = 1; off < 1024; off <<= 1) {
        int v0 = (t >= off) ? sc[0][t - off] : 0;
        int v1 = (t >= off) ? sc[1][t - off] : 0;
        int v2 = (t >= off) ? sc[2][t - off] : 0;
        __syncthreads();
        sc[0][t] += v0; sc[1][t] += v1; sc[2][t] += v2;
        __syncthreads();
    }

    const int T1 = sc[0][1023], T2 = sc[1][1023], T3 = sc[2][1023];
    int p3 = sc[2][t] - n3;
    int p2 = T3 + (sc[1][t] - n2);
    int p1 = T3 + T2 + (sc[0][t] - n1);

    int* ord = g_order + b * LL;
    for (int i = l0; i < l1; i++) {
        int k = key[i];
        if (k == 3)      ord[p3++] = i;
        else if (k == 2) ord[p2++] = i;
        else if (k == 1) ord[p1++] = i;
    }
    if (t == 0) g_cnt[b] = T1 + T2 + T3;
}

// ---------------------------------------------------------------------------
// Output writer
// ---------------------------------------------------------------------------
__global__ void out_writer(const float* __restrict__ lines,
                           float* __restrict__ out, int out_size)
{
    const int gid = blockIdx.x * blockDim.x + threadIdx.x;

    if (gid < BB * N_OUT) {
        int b = gid / N_OUT, r = gid - b * N_OUT;
        int cnt = g_cnt[b];
        float4 lo = {0.f, 0.f, 0.f, 0.f};
        float4 so = {0.f, 0.f, 0.f, 0.f};
        if (cnt > 0) {
            int idx = g_order[b * LL + (r % cnt)];
            lo = *(const float4*)(lines + (size_t)(b * LL + idx) * 4);
            so = *(const float4*)(g_s + (size_t)(b * LL + idx) * 4);
        }
        *(float4*)(out + (size_t)gid * 4) = lo;
        if (out_size >= 2 * 4 * BB * N_OUT)
            *(float4*)(out + (size_t)(BB * N_OUT + gid) * 4) = so;
    }
    int g2 = gid - BB * N_OUT;
    if (g2 >= 0 && g2 < NROWS && out_size >= 8 * BB * N_OUT + 4 * NROWS) {
        *(float4*)(out + (size_t)(2 * BB * N_OUT + g2) * 4) =
            *(const float4*)(g_s + (size_t)g2 * 4);
    }
}

// ---------------------------------------------------------------------------
// Launch
// ---------------------------------------------------------------------------
extern "C" void kernel_launch(void* const* d_in, const int* in_sizes, int n_in,
                              void* d_out, int out_size)
{
    const float* feature = (const float*)d_in[0];
    const float* lines   = (const float*)d_in[1];
    const float* fc1_w   = (const float*)d_in[2];
    const float* fc1_b   = (const float*)d_in[3];
    const float* w1      = (const float*)d_in[4];
    const float* b1      = (const float*)d_in[5];
    const float* w2      = (const float*)d_in[6];
    const float* b2      = (const float*)d_in[7];
    const float* w3      = (const float*)d_in[8];
    const float* b3      = (const float*)d_in[9];
    float* out = (float*)d_out;

    float *x_p, *feat_p, *h1_p, *h2_p, *wt_p;
    cudaGetSymbolAddress((void**)&x_p,    g_x);
    cudaGetSymbolAddress((void**)&feat_p, g_feat);
    cudaGetSymbolAddress((void**)&h1_p,   g_h1);
    cudaGetSymbolAddress((void**)&h2_p,   g_h2);
    cudaGetSymbolAddress((void**)&wt_p,   g_wfc1T);

    cudaFuncSetAttribute(gemm_mma3, cudaFuncAttributeMaxDynamicSharedMemorySize,
                         SMEM_GEMM);
    cudaFuncSetAttribute(gemm_fc1, cudaFuncAttributeMaxDynamicSharedMemorySize,
                         SMEM_GEMM);

    // fc1_w -> [k][n]
    transpose_fc1<<<dim3(8, 4), dim3(32, 8)>>>(fc1_w, wt_p);

    // fc1 on tensor cores (3xBF16, K-chunk 32)
    gemm_fc1<<<dim3(1, HW / 128, BB), 256, SMEM_GEMM>>>(feature, wt_p, fc1_b, x_p);

    // bilinear sample + maxpool -> feat
    sample_kernel<<<NROWS, DIM_LOI>>>(lines, feat_p);

    // MLP layers 1 & 2 (3xBF16 mma, K-chunk 32)
    gemm_mma3<<<dim3(8, NPAD / 128), 256, SMEM_GEMM>>>(feat_p, w1, b1, h1_p);
    gemm_mma3<<<dim3(8, NPAD / 128), 256, SMEM_GEMM>>>(h1_p, w2, b2, h2_p);

    // final layer + softmax + keep/key
    layer3_kernel<<<NROWS, 128>>>(h2_p, w3, b3);

    // stable bucket sort per batch
    select_kernel<<<BB, 1024>>>();

    // outputs
    int tot = BB * N_OUT + NROWS;
    out_writer<<<(tot + 255) / 256, 256>>>(lines, out, out_size);
}

// round 14
// speedup vs baseline: 1.0522x; 1.0522x over previous
#include <cuda_runtime.h>
#include <cuda_bf16.h>
#include <cstdint>

// ---------------------------------------------------------------------------
// Problem constants
// ---------------------------------------------------------------------------
#define BB        4
#define LL        5000
#define HH        256
#define WW        256
#define HW        (HH * WW)          // 65536
#define C_IN      256
#define DIM_LOI   128
#define N_PTS0    32
#define N_PTS1    8
#define DIM_FC    1024
#define N_OUT     2500
#define NROWS     (BB * LL)          // 20000
#define NPAD      20096              // 157 * 128

// ---------------------------------------------------------------------------
// Static scratch (no allocations allowed)
// ---------------------------------------------------------------------------
__device__ float g_x[(size_t)BB * HW * DIM_LOI];      // fc1 out, pixel-major [b][hw][c]
__device__ __nv_bfloat16 g_feat_h[(size_t)NPAD * DIM_FC];  // split activations
__device__ __nv_bfloat16 g_feat_l[(size_t)NPAD * DIM_FC];
__device__ __nv_bfloat16 g_h1_h[(size_t)NPAD * DIM_FC];
__device__ __nv_bfloat16 g_h1_l[(size_t)NPAD * DIM_FC];
__device__ float g_h2[(size_t)NPAD * DIM_FC];
__device__ uint32_t g_w1ph[(size_t)512 * DIM_FC];     // packed bf16 pair weights
__device__ uint32_t g_w1pl[(size_t)512 * DIM_FC];
__device__ uint32_t g_w2ph[(size_t)512 * DIM_FC];
__device__ uint32_t g_w2pl[(size_t)512 * DIM_FC];
__device__ float g_wfc1T[(size_t)C_IN * DIM_LOI];     // fc1_w transposed [k][n]
__device__ float g_s[(size_t)NROWS * 4];              // softmax scores
__device__ int   g_key[NROWS];
__device__ int   g_order[BB * LL];
__device__ int   g_cnt[BB];

// ---------------------------------------------------------------------------
// helpers
// ---------------------------------------------------------------------------
__device__ __forceinline__ uint32_t smem_u32(const void* p) {
    uint32_t a;
    asm("{ .reg .u64 t; cvta.to.shared.u64 t, %1; cvt.u32.u64 %0, t; }" : "=r"(a) : "l"(p));
    return a;
}
__device__ __forceinline__ void ldsm4(uint32_t r[4], uint32_t addr) {
    asm volatile("ldmatrix.sync.aligned.m8n8.x4.shared.b16 {%0,%1,%2,%3}, [%4];"
                 : "=r"(r[0]), "=r"(r[1]), "=r"(r[2]), "=r"(r[3]) : "r"(addr));
}
__device__ __forceinline__ void mma_bf16(float* c, const uint32_t* a, const uint32_t* b) {
    asm volatile(
        "mma.sync.aligned.m16n8k16.row.col.f32.bf16.bf16.f32 "
        "{%0,%1,%2,%3}, {%4,%5,%6,%7}, {%8,%9}, {%0,%1,%2,%3};"
        : "+f"(c[0]), "+f"(c[1]), "+f"(c[2]), "+f"(c[3])
        : "r"(a[0]), "r"(a[1]), "r"(a[2]), "r"(a[3]), "r"(b[0]), "r"(b[1]));
}
__device__ __forceinline__ void split_bf(float v, uint32_t& h, uint32_t& l) {
    __nv_bfloat16 hb = __float2bfloat16_rn(v);
    float r = v - __bfloat162float(hb);
    __nv_bfloat16 lb = __float2bfloat16_rn(r);
    h = (uint32_t)*(uint16_t*)&hb;
    l = (uint32_t)*(uint16_t*)&lb;
}
__device__ __forceinline__ uint32_t bpack(uint32_t lo16, uint32_t hi16) {
    return lo16 | (hi16 << 16);
}
__device__ __forceinline__ void cp16(uint32_t dst, const void* src) {
    asm volatile("cp.async.cg.shared.global [%0], [%1], 16;"
                 :: "r"(dst), "l"(src) : "memory");
}
__device__ __forceinline__ void cp_commit() {
    asm volatile("cp.async.commit_group;" ::: "memory");
}
template<int N>
__device__ __forceinline__ void cp_wait() {
    asm volatile("cp.async.wait_group %0;" :: "n"(N) : "memory");
}

// ---------------------------------------------------------------------------
// bf16 smem geometry (K-chunk 16): A 128x16 bf16 rows, 48B stride
// (conflict-free LDSM); B 8 packed-pair rows [k/2][n] u32, 136-u32 stride.
// ---------------------------------------------------------------------------
#define AROWB 48
#define ST_AB (128 * AROWB)             // 6144 B
#define BSTRU 136
#define ST_BB (8 * BSTRU * 4)           // 4352 B
#define STAGE_B (2 * ST_AB + 2 * ST_BB) // 20992 B
#define NSTG  3
#define SMEM_MLP (NSTG * STAGE_B)       // 62976 B (2 CTAs: 126 KB)
#define SMEM_FC1 (2 * STAGE_B)          // 41984 B
// stage layout: Ah @0, Al @ST_AB, Bh @2*ST_AB, Bl @2*ST_AB+ST_BB

// bf16 LDSM lane offset (bytes)
__device__ __forceinline__ int ldsm_lane_off_bf(int lane) {
    int row = (((lane >> 3) & 1) << 3) + (lane & 7);
    int colB = (lane >> 4) << 4;
    return row * AROWB + colB;
}

// ---------------------------------------------------------------------------
// 3xBF16 compute on a 128x16 stage: 8 ldsm + 16 LDS + 48 MMA / warp.
// ---------------------------------------------------------------------------
__device__ __forceinline__ void compute_stage_bf(
    uint32_t AhU, uint32_t AlU,
    const uint32_t* __restrict__ Bhp, const uint32_t* __restrict__ Blp,
    int warp_n, int gr, int tg, float acc[4][4][4])
{
    uint32_t bh[4][2], bl[4][2];
#pragma unroll
    for (int nt = 0; nt < 4; nt++) {
        int c = warp_n + nt * 8 + gr;
        bh[nt][0] = Bhp[tg * BSTRU + c];
        bh[nt][1] = Bhp[(tg + 4) * BSTRU + c];
        bl[nt][0] = Blp[tg * BSTRU + c];
        bl[nt][1] = Blp[(tg + 4) * BSTRU + c];
    }
#pragma unroll
    for (int mt = 0; mt < 4; mt++) {
        uint32_t ah[4], al[4];
        const uint32_t off = (uint32_t)(mt * 16 * AROWB);
        ldsm4(ah, AhU + off);
        ldsm4(al, AlU + off);
#pragma unroll
        for (int nt = 0; nt < 4; nt++) {
            mma_bf16(acc[mt][nt], ah, bh[nt]);
            mma_bf16(acc[mt][nt], ah, bl[nt]);
            mma_bf16(acc[mt][nt], al, bh[nt]);
        }
    }
}

// ---------------------------------------------------------------------------
// MLP GEMM (3xBF16, cp.async loader, pre-split inputs):
//   C = relu((Ah+Al) @ (Wh+Wl) + bias)
// A: bf16 hi/lo [M][1024]; W: packed-pair u32 hi/lo [512][1024].
// SPLIT_OUT=1: write split bf16 hi/lo; SPLIT_OUT=0: write f32.
// Block tile 128x128, 256 thr, 3-stage cp.async pipeline, 2 CTAs/SM.
// ---------------------------------------------------------------------------
template<int SPLIT_OUT>
__global__ __launch_bounds__(256, 2)
void gemm_bf(const __nv_bfloat16* __restrict__ Ah_, const __nv_bfloat16* __restrict__ Al_,
             const uint32_t* __restrict__ Wph, const uint32_t* __restrict__ Wpl,
             const float* __restrict__ bias,
             float* __restrict__ C, __nv_bfloat16* __restrict__ Ch,
             __nv_bfloat16* __restrict__ Cl)
{
    extern __shared__ __align__(16) char sm[];
    const uint32_t sb = smem_u32(sm);

    const int tid  = threadIdx.x;
    const int lane = tid & 31;
    const int wid  = tid >> 5;
    const int m0   = blockIdx.y * 128;
    const int n0   = blockIdx.x * 128;
    const int warp_m = (wid & 1) * 64;
    const int warp_n = (wid >> 1) * 32;
    const int gr = lane >> 2;
    const int tg = lane & 3;
    const uint32_t AU0 = sb + (uint32_t)(warp_m * AROWB + ldsm_lane_off_bf(lane));

    float acc[4][4][4];
#pragma unroll
    for (int mt = 0; mt < 4; mt++)
#pragma unroll
        for (int nt = 0; nt < 4; nt++)
#pragma unroll
            for (int r = 0; r < 4; r++) acc[mt][nt][r] = 0.f;

    // A loader: tid -> row = tid&127, sel = tid>>7 (0=hi array, 1=lo array)
    const int a_row = tid & 127;
    const int a_sel = tid >> 7;
    const __nv_bfloat16* Asrc =
        (a_sel ? Al_ : Ah_) + (size_t)(m0 + a_row) * 1024;
    const uint32_t a_dst = (uint32_t)(a_sel * ST_AB + a_row * AROWB);
    // B loader: p = pair-row 0..7, 4 consecutive n (16B) from hi AND lo
    const int b_p  = tid >> 5;
    const int b_nw = (tid & 31) << 2;     // u32 (= n col) offset
    const uint32_t* Bh_src = Wph + (size_t)b_p * 1024 + n0 + b_nw;
    const uint32_t* Bl_src = Wpl + (size_t)b_p * 1024 + n0 + b_nw;
    const uint32_t b_dst = (uint32_t)(2 * ST_AB + (b_p * BSTRU + b_nw) * 4);

    auto issue_chunk = [&](int ch) {
        const uint32_t st = sb + (uint32_t)((ch % 3) * STAGE_B) - sb
                          + sb;  // keep simple below
        const uint32_t stg = sb + (uint32_t)((ch % 3) * STAGE_B);
        const __nv_bfloat16* as = Asrc + (size_t)ch * 16;
        cp16(stg + a_dst, as);
        cp16(stg + a_dst + 16, as + 8);
        const size_t bko = (size_t)ch * 8 * 1024;
        cp16(stg + b_dst, Bh_src + bko);
        cp16(stg + b_dst + ST_BB, Bl_src + bko);
        cp_commit();
        (void)st;
    };
    auto compute_chunk = [&](int p) {
        const char* st = sm + p * STAGE_B;
        compute_stage_bf(AU0 + (uint32_t)(p * STAGE_B),
                         AU0 + (uint32_t)(p * STAGE_B + ST_AB),
                         (const uint32_t*)(st + 2 * ST_AB),
                         (const uint32_t*)(st + 2 * ST_AB + ST_BB),
                         warp_n, gr, tg, acc);
    };

    issue_chunk(0);
    issue_chunk(1);

    int s_comp = 0;
    for (int ch = 0; ch < 64; ch++) {
        if (ch < 63) cp_wait<1>(); else cp_wait<0>();
        __syncthreads();
        if (ch + 2 < 64) issue_chunk(ch + 2);
        compute_chunk(s_comp);
        s_comp = (s_comp == 2) ? 0 : s_comp + 1;
    }

    // ---- epilogue: bias + relu (+ optional split)
#pragma unroll
    for (int mt = 0; mt < 4; mt++) {
        int row = m0 + warp_m + mt * 16 + gr;
#pragma unroll
        for (int nt = 0; nt < 4; nt++) {
            int col = n0 + warp_n + nt * 8 + tg * 2;
            float b0 = bias[col], b1 = bias[col + 1];
            float v00 = fmaxf(acc[mt][nt][0] + b0, 0.f);
            float v01 = fmaxf(acc[mt][nt][1] + b1, 0.f);
            float v10 = fmaxf(acc[mt][nt][2] + b0, 0.f);
            float v11 = fmaxf(acc[mt][nt][3] + b1, 0.f);
            size_t o0 = (size_t)row * 1024 + col;
            size_t o1 = (size_t)(row + 8) * 1024 + col;
            if (SPLIT_OUT) {
                uint32_t h0, l0, h1, l1;
                split_bf(v00, h0, l0); split_bf(v01, h1, l1);
                *(uint32_t*)(Ch + o0) = bpack(h0, h1);
                *(uint32_t*)(Cl + o0) = bpack(l0, l1);
                split_bf(v10, h0, l0); split_bf(v11, h1, l1);
                *(uint32_t*)(Ch + o1) = bpack(h0, h1);
                *(uint32_t*)(Cl + o1) = bpack(l0, l1);
            } else {
                *(float2*)(C + o0) = make_float2(v00, v01);
                *(float2*)(C + o1) = make_float2(v10, v11);
            }
        }
    }
}

// ---------------------------------------------------------------------------
// fc1 GEMM (3xBF16, register loader, K-chunk 16 — R12 version)
// ---------------------------------------------------------------------------
__global__ __launch_bounds__(256, 2)
void gemm_fc1(const float* __restrict__ feature, const float* __restrict__ Wt,
              const float* __restrict__ bias, float* __restrict__ X)
{
    extern __shared__ __align__(16) char sm[];

    const int tid  = threadIdx.x;
    const int lane = tid & 31;
    const int wid  = tid >> 5;
    const int b    = blockIdx.z;
    const int m0   = blockIdx.y * 128;
    const int warp_m = (wid & 1) * 64;
    const int warp_n = (wid >> 1) * 32;
    const int gr = lane >> 2;
    const int tg = lane & 3;
    const uint32_t AU0 = smem_u32(sm)
        + (uint32_t)(warp_m * AROWB + ldsm_lane_off_bf(lane));

    const float* Ab = feature + (size_t)b * C_IN * HW;
    float* Cb = X + (size_t)b * HW * DIM_LOI;

    float acc[4][4][4];
#pragma unroll
    for (int mt = 0; mt < 4; mt++)
#pragma unroll
        for (int nt = 0; nt < 4; nt++)
#pragma unroll
            for (int r = 0; r < 4; r++) acc[mt][nt][r] = 0.f;

    const int a_m  = tid & 127;
    const int a_kh = (tid >> 7) << 3;
    const int b_k0 = (tid >> 5) << 1;
    const int b_n4 = (tid & 31) << 2;

    const float* Acol = Ab + (size_t)a_kh * HW + m0 + a_m;
    const float* Brow0 = Wt + (size_t)b_k0 * 128 + b_n4;
    const float* Brow1 = Wt + (size_t)(b_k0 + 1) * 128 + b_n4;

    float ra[8];
    float4 rb0, rb1;

    auto load_chunk = [&](int ch) {
        const size_t ko = (size_t)ch * 16;
#pragma unroll
        for (int j = 0; j < 8; j++)
            ra[j] = Acol[(ko + j) * HW];
        rb0 = *(const float4*)(Brow0 + ko * 128);
        rb1 = *(const float4*)(Brow1 + ko * 128);
    };
    auto store_chunk = [&](int p) {
        char* st = sm + p * STAGE_B;
        {
            uint32_t h[8], l[8];
#pragma unroll
            for (int j = 0; j < 8; j++) split_bf(ra[j], h[j], l[j]);
            uint4 hv = make_uint4(bpack(h[0], h[1]), bpack(h[2], h[3]),
                                  bpack(h[4], h[5]), bpack(h[6], h[7]));
            uint4 lv = make_uint4(bpack(l[0], l[1]), bpack(l[2], l[3]),
                                  bpack(l[4], l[5]), bpack(l[6], l[7]));
            int off = a_m * AROWB + a_kh * 2;
            *(uint4*)(st + off) = hv;
            *(uint4*)(st + ST_AB + off) = lv;
        }
        {
            uint32_t ha, la, hb, lb;
            uint4 hv, lv;
            split_bf(rb0.x, ha, la); split_bf(rb1.x, hb, lb);
            hv.x = bpack(ha, hb); lv.x = bpack(la, lb);
            split_bf(rb0.y, ha, la); split_bf(rb1.y, hb, lb);
            hv.y = bpack(ha, hb); lv.y = bpack(la, lb);
            split_bf(rb0.z, ha, la); split_bf(rb1.z, hb, lb);
            hv.z = bpack(ha, hb); lv.z = bpack(la, lb);
            split_bf(rb0.w, ha, la); split_bf(rb1.w, hb, lb);
            hv.w = bpack(ha, hb); lv.w = bpack(la, lb);
            int off = ((b_k0 >> 1) * BSTRU + b_n4) * 4;
            *(uint4*)(st + 2 * ST_AB + off) = hv;
            *(uint4*)(st + 2 * ST_AB + ST_BB + off) = lv;
        }
    };
    auto compute_chunk = [&](int p) {
        const char* st = sm + p * STAGE_B;
        compute_stage_bf(AU0 + (uint32_t)(p * STAGE_B),
                         AU0 + (uint32_t)(p * STAGE_B + ST_AB),
                         (const uint32_t*)(st + 2 * ST_AB),
                         (const uint32_t*)(st + 2 * ST_AB + ST_BB),
                         warp_n, gr, tg, acc);
    };

    load_chunk(0);
    store_chunk(0);
    __syncthreads();

    for (int ch = 1; ch <= 16; ch++) {
        if (ch < 16) load_chunk(ch);
        compute_chunk((ch - 1) & 1);
        if (ch < 16) store_chunk(ch & 1);
        __syncthreads();
    }

#pragma unroll
    for (int mt = 0; mt < 4; mt++) {
        int row = m0 + warp_m + mt * 16 + gr;
#pragma unroll
        for (int nt = 0; nt < 4; nt++) {
            int col = warp_n + nt * 8 + tg * 2;
            float b0 = bias[col], b1 = bias[col + 1];
            float2 v0, v1;
            v0.x = acc[mt][nt][0] + b0;
            v0.y = acc[mt][nt][1] + b1;
            v1.x = acc[mt][nt][2] + b0;
            v1.y = acc[mt][nt][3] + b1;
            *(float2*)(Cb + (size_t)row * 128 + col) = v0;
            *(float2*)(Cb + (size_t)(row + 8) * 128 + col) = v1;
        }
    }
}

// ---------------------------------------------------------------------------
// Weight prep
// ---------------------------------------------------------------------------
__global__ __launch_bounds__(256)
void transpose_fc1(const float* __restrict__ s, float* __restrict__ d)
{
    __shared__ float t[32][33];
    const int bx = blockIdx.x * 32;   // k
    const int by = blockIdx.y * 32;   // n
    const int tx = threadIdx.x, ty = threadIdx.y;
#pragma unroll
    for (int r = 0; r < 32; r += 8)
        t[ty + r][tx] = s[(size_t)(by + ty + r) * 256 + bx + tx];
    __syncthreads();
#pragma unroll
    for (int r = 0; r < 32; r += 8)
        d[(size_t)(bx + ty + r) * 128 + by + tx] = t[tx][ty + r];
}

// pack w [1024][1024] -> pair-packed u32 hi/lo [512][1024]
__global__ __launch_bounds__(256)
void pack_w(const float* __restrict__ w, uint32_t* __restrict__ ph,
            uint32_t* __restrict__ pl)
{
    int i = blockIdx.x * blockDim.x + threadIdx.x;
    if (i >= 512 * 1024) return;
    int k2 = i >> 10, n = i & 1023;
    float a = w[(size_t)(2 * k2) * 1024 + n];
    float c = w[(size_t)(2 * k2 + 1) * 1024 + n];
    uint32_t ha, la, hc, lc;
    split_bf(a, ha, la);
    split_bf(c, hc, lc);
    ph[i] = bpack(ha, hc);
    pl[i] = bpack(la, lc);
}

// ---------------------------------------------------------------------------
// Bilinear sampling + maxpool -> split bf16 feature rows.
// ---------------------------------------------------------------------------
__global__ __launch_bounds__(128)
void sample_kernel(const float* __restrict__ lines,
                   __nv_bfloat16* __restrict__ fh, __nv_bfloat16* __restrict__ fl)
{
    const int bl = blockIdx.x;
    const int b  = bl / LL;
    const int c  = threadIdx.x;

    const float* xb = g_x + (size_t)b * HW * DIM_LOI;

    float4 ln = *(const float4*)(lines + (size_t)bl * 4);
    const float x0 = ln.x, y0 = ln.y, x1 = ln.z, y1 = ln.w;

    __shared__ float stage[DIM_LOI * N_PTS1];

    float maxv = 0.f;
#pragma unroll 4
    for (int pt = 0; pt < N_PTS0; pt++) {
        float lam = (float)pt * (1.0f / 31.0f);
        float px = x0 * lam + x1 * (1.0f - lam) - 0.5f;
        float py = y0 * lam + y1 * (1.0f - lam) - 0.5f;

        float px0 = fminf(fmaxf(floorf(px), 0.f), (float)(HH - 1));
        float py0 = fminf(fmaxf(floorf(py), 0.f), (float)(WW - 1));
        float px1 = fminf(px0 + 1.f, (float)(HH - 1));
        float py1 = fminf(py0 + 1.f, (float)(WW - 1));
        int ix0 = (int)px0, iy0 = (int)py0, ix1 = (int)px1, iy1 = (int)py1;

        float w00 = (px1 - px) * (py1 - py);
        float w10 = (px - px0) * (py1 - py);
        float w01 = (px1 - px) * (py - py0);
        float w11 = (px - px0) * (py - py0);

        const float* t00 = xb + (size_t)(ix0 * WW + iy0) * DIM_LOI + c;
        const float* t10 = xb + (size_t)(ix1 * WW + iy0) * DIM_LOI + c;
        const float* t01 = xb + (size_t)(ix0 * WW + iy1) * DIM_LOI + c;
        const float* t11 = xb + (size_t)(ix1 * WW + iy1) * DIM_LOI + c;
        float v = w00 * (*t00) + w10 * (*t10) + w01 * (*t01) + w11 * (*t11);

        if ((pt & 3) == 0) maxv = v; else maxv = fmaxf(maxv, v);
        if ((pt & 3) == 3) stage[c * N_PTS1 + (pt >> 2)] = maxv;
    }
    __syncthreads();

    __nv_bfloat16* fhr = fh + (size_t)bl * DIM_FC;
    __nv_bfloat16* flr = fl + (size_t)bl * DIM_FC;
    for (int i = c; i < DIM_FC; i += DIM_LOI) {
        uint32_t h, l;
        split_bf(stage[i], h, l);
        uint16_t hu = (uint16_t)h, lu = (uint16_t)l;
        fhr[i] = *(__nv_bfloat16*)&hu;
        flr[i] = *(__nv_bfloat16*)&lu;
    }
}

// ---------------------------------------------------------------------------
// Final layer (1024 -> 4) + softmax + keep/key.
// ---------------------------------------------------------------------------
__global__ __launch_bounds__(128)
void layer3_kernel(const float* __restrict__ h2, const float* __restrict__ w3,
                   const float* __restrict__ b3)
{
    const int row = blockIdx.x;
    const int tid = threadIdx.x;
    const float* hr = h2 + (size_t)row * DIM_FC;

    float acc[4] = {0.f, 0.f, 0.f, 0.f};
    for (int k = tid; k < DIM_FC; k += 128) {
        float hv = hr[k];
        float4 wv = *(const float4*)(w3 + (size_t)k * 4);
        acc[0] += hv * wv.x; acc[1] += hv * wv.y;
        acc[2] += hv * wv.z; acc[3] += hv * wv.w;
    }
#pragma unroll
    for (int off = 16; off; off >>= 1)
#pragma unroll
        for (int n = 0; n < 4; n++)
            acc[n] += __shfl_down_sync(0xffffffffu, acc[n], off);

    __shared__ float red[4][4];
    if ((tid & 31) == 0)
#pragma unroll
        for (int n = 0; n < 4; n++) red[tid >> 5][n] = acc[n];
    __syncthreads();

    if (tid == 0) {
        float lg[4];
#pragma unroll
        for (int n = 0; n < 4; n++)
            lg[n] = red[0][n] + red[1][n] + red[2][n] + red[3][n] + b3[n];
        float mx = fmaxf(fmaxf(lg[0], lg[1]), fmaxf(lg[2], lg[3]));
        float e[4], sum = 0.f;
#pragma unroll
        for (int n = 0; n < 4; n++) { e[n] = __expf(lg[n] - mx); sum += e[n]; }
        float inv = 1.0f / sum;
        float s0 = e[0] * inv, s1 = e[1] * inv, s2 = e[2] * inv, s3 = e[3] * inv;
        float4 sv = {s0, s1, s2, s3};
        *(float4*)(g_s + (size_t)row * 4) = sv;

        bool keep = ((s1 > 0.25f) || (s2 > 0.25f) || (s3 > 0.25f)) && (s0 < 0.25f);
        int am = 0; float best = s0;
        if (s1 > best) { best = s1; am = 1; }
        if (s2 > best) { best = s2; am = 2; }
        if (s3 > best) { best = s3; am = 3; }
        g_key[row] = keep ? am : -1;
    }
}

// ---------------------------------------------------------------------------
// Stable counting sort by key desc (buckets 3,2,1). One block per batch.
// ---------------------------------------------------------------------------
__global__ __launch_bounds__(1024)
void select_kernel()
{
    const int b = blockIdx.x;
    const int t = threadIdx.x;
    const int* key = g_key + b * LL;

    __shared__ int sc[3][1024];

    const int l0 = t * 5;
    const int l1 = min(l0 + 5, LL);
    int n1 = 0, n2 = 0, n3 = 0;
    for (int i = l0; i < l1; i++) {
        int k = key[i];
        n1 += (k == 1); n2 += (k == 2); n3 += (k == 3);
    }
    sc[0][t] = n1; sc[1][t] = n2; sc[2][t] = n3;
    __syncthreads();

    for (int off = 1; off < 1024; off <<= 1) {
        int v0 = (t >= off) ? sc[0][t - off] : 0;
        int v1 = (t >= off) ? sc[1][t - off] : 0;
        int v2 = (t >= off) ? sc[2][t - off] : 0;
        __syncthreads();
        sc[0][t] += v0; sc[1][t] += v1; sc[2][t] += v2;
        __syncthreads();
    }

    const int T1 = sc[0][1023], T2 = sc[1][1023], T3 = sc[2][1023];
    int p3 = sc[2][t] - n3;
    int p2 = T3 + (sc[1][t] - n2);
    int p1 = T3 + T2 + (sc[0][t] - n1);

    int* ord = g_order + b * LL;
    for (int i = l0; i < l1; i++) {
        int k = key[i];
        if (k == 3)      ord[p3++] = i;
        else if (k == 2) ord[p2++] = i;
        else if (k == 1) ord[p1++] = i;
    }
    if (t == 0) g_cnt[b] = T1 + T2 + T3;
}

// ---------------------------------------------------------------------------
// Output writer
// ---------------------------------------------------------------------------
__global__ void out_writer(const float* __restrict__ lines,
                           float* __restrict__ out, int out_size)
{
    const int gid = blockIdx.x * blockDim.x + threadIdx.x;

    if (gid < BB * N_OUT) {
        int b = gid / N_OUT, r = gid - b * N_OUT;
        int cnt = g_cnt[b];
        float4 lo = {0.f, 0.f, 0.f, 0.f};
        float4 so = {0.f, 0.f, 0.f, 0.f};
        if (cnt > 0) {
            int idx = g_order[b * LL + (r % cnt)];
            lo = *(const float4*)(lines + (size_t)(b * LL + idx) * 4);
            so = *(const float4*)(g_s + (size_t)(b * LL + idx) * 4);
        }
        *(float4*)(out + (size_t)gid * 4) = lo;
        if (out_size >= 2 * 4 * BB * N_OUT)
            *(float4*)(out + (size_t)(BB * N_OUT + gid) * 4) = so;
    }
    int g2 = gid - BB * N_OUT;
    if (g2 >= 0 && g2 < NROWS && out_size >= 8 * BB * N_OUT + 4 * NROWS) {
        *(float4*)(out + (size_t)(2 * BB * N_OUT + g2) * 4) =
            *(const float4*)(g_s + (size_t)g2 * 4);
    }
}

// ---------------------------------------------------------------------------
// Launch
// ---------------------------------------------------------------------------
extern "C" void kernel_launch(void* const* d_in, const int* in_sizes, int n_in,
                              void* d_out, int out_size)
{
    const float* feature = (const float*)d_in[0];
    const float* lines   = (const float*)d_in[1];
    const float* fc1_w   = (const float*)d_in[2];
    const float* fc1_b   = (const float*)d_in[3];
    const float* w1      = (const float*)d_in[4];
    const float* b1      = (const float*)d_in[5];
    const float* w2      = (const float*)d_in[6];
    const float* b2      = (const float*)d_in[7];
    const float* w3      = (const float*)d_in[8];
    const float* b3      = (const float*)d_in[9];
    float* out = (float*)d_out;

    float *x_p, *h2_p, *wt_p;
    __nv_bfloat16 *fh_p, *fl_p, *h1h_p, *h1l_p;
    uint32_t *w1ph_p, *w1pl_p, *w2ph_p, *w2pl_p;
    cudaGetSymbolAddress((void**)&x_p,    g_x);
    cudaGetSymbolAddress((void**)&fh_p,   g_feat_h);
    cudaGetSymbolAddress((void**)&fl_p,   g_feat_l);
    cudaGetSymbolAddress((void**)&h1h_p,  g_h1_h);
    cudaGetSymbolAddress((void**)&h1l_p,  g_h1_l);
    cudaGetSymbolAddress((void**)&h2_p,   g_h2);
    cudaGetSymbolAddress((void**)&wt_p,   g_wfc1T);
    cudaGetSymbolAddress((void**)&w1ph_p, g_w1ph);
    cudaGetSymbolAddress((void**)&w1pl_p, g_w1pl);
    cudaGetSymbolAddress((void**)&w2ph_p, g_w2ph);
    cudaGetSymbolAddress((void**)&w2pl_p, g_w2pl);

    cudaFuncSetAttribute(gemm_bf<0>, cudaFuncAttributeMaxDynamicSharedMemorySize,
                         SMEM_MLP);
    cudaFuncSetAttribute(gemm_bf<1>, cudaFuncAttributeMaxDynamicSharedMemorySize,
                         SMEM_MLP);
    cudaFuncSetAttribute(gemm_fc1, cudaFuncAttributeMaxDynamicSharedMemorySize,
                         SMEM_FC1);

    // weight prep
    transpose_fc1<<<dim3(8, 4), dim3(32, 8)>>>(fc1_w, wt_p);
    pack_w<<<2048, 256>>>(w1, w1ph_p, w1pl_p);
    pack_w<<<2048, 256>>>(w2, w2ph_p, w2pl_p);

    // fc1 on tensor cores
    gemm_fc1<<<dim3(1, HW / 128, BB), 256, SMEM_FC1>>>(feature, wt_p, fc1_b, x_p);

    // bilinear sample + maxpool -> split bf16 feat
    sample_kernel<<<NROWS, DIM_LOI>>>(lines, fh_p, fl_p);

    // MLP layers 1 & 2 (3xBF16, cp.async loaders)
    gemm_bf<1><<<dim3(8, NPAD / 128), 256, SMEM_MLP>>>(
        fh_p, fl_p, w1ph_p, w1pl_p, b1, nullptr, h1h_p, h1l_p);
    gemm_bf<0><<<dim3(8, NPAD / 128), 256, SMEM_MLP>>>(
        h1h_p, h1l_p, w2ph_p, w2pl_p, b2, h2_p, nullptr, nullptr);

    // final layer + softmax + keep/key
    layer3_kernel<<<NROWS, 128>>>(h2_p, w3, b3);

    // stable bucket sort per batch
    select_kernel<<<BB, 1024>>>();

    // outputs
    int tot = BB * N_OUT + NROWS;
    out_writer<<<(tot + 255) / 256, 256>>>(lines, out, out_size);
}

// round 15
// speedup vs baseline: 1.1158x; 1.0605x over previous
#include <cuda_runtime.h>
#include <cuda_bf16.h>
#include <cstdint>

// ---------------------------------------------------------------------------
// Problem constants
// ---------------------------------------------------------------------------
#define BB        4
#define LL        5000
#define HH        256
#define WW        256
#define HW        (HH * WW)          // 65536
#define C_IN      256
#define DIM_LOI   128
#define N_PTS0    32
#define N_PTS1    8
#define DIM_FC    1024
#define N_OUT     2500
#define NROWS     (BB * LL)          // 20000
#define NPAD      20096              // 157 * 128

// ---------------------------------------------------------------------------
// Static scratch (no allocations allowed)
// ---------------------------------------------------------------------------
__device__ float g_x[(size_t)BB * HW * DIM_LOI];      // fc1 out, pixel-major [b][hw][c]
__device__ float g_feat[(size_t)NPAD * DIM_FC];       // pooled features (pad rows stay 0)
__device__ float g_h1[(size_t)NPAD * DIM_FC];
__device__ float g_part[(size_t)NPAD * 32 * 4];       // partial logits [row][32][4]
__device__ float g_wfc1T[(size_t)C_IN * DIM_LOI];     // fc1_w transposed [k][n]
__device__ float g_s[(size_t)NROWS * 4];              // softmax scores
__device__ int   g_key[NROWS];
__device__ int   g_order[BB * LL];
__device__ int   g_cnt[BB];

// ---------------------------------------------------------------------------
// helpers
// ---------------------------------------------------------------------------
__device__ __forceinline__ uint32_t smem_u32(const void* p) {
    uint32_t a;
    asm("{ .reg .u64 t; cvta.to.shared.u64 t, %1; cvt.u32.u64 %0, t; }" : "=r"(a) : "l"(p));
    return a;
}
__device__ __forceinline__ void ldsm4(uint32_t r[4], uint32_t addr) {
    asm volatile("ldmatrix.sync.aligned.m8n8.x4.shared.b16 {%0,%1,%2,%3}, [%4];"
                 : "=r"(r[0]), "=r"(r[1]), "=r"(r[2]), "=r"(r[3]) : "r"(addr));
}
__device__ __forceinline__ void mma_bf16(float* c, const uint32_t* a, const uint32_t* b) {
    asm volatile(
        "mma.sync.aligned.m16n8k16.row.col.f32.bf16.bf16.f32 "
        "{%0,%1,%2,%3}, {%4,%5,%6,%7}, {%8,%9}, {%0,%1,%2,%3};"
        : "+f"(c[0]), "+f"(c[1]), "+f"(c[2]), "+f"(c[3])
        : "r"(a[0]), "r"(a[1]), "r"(a[2]), "r"(a[3]), "r"(b[0]), "r"(b[1]));
}
__device__ __forceinline__ void split_bf(float v, uint32_t& h, uint32_t& l) {
    __nv_bfloat16 hb = __float2bfloat16_rn(v);
    float r = v - __bfloat162float(hb);
    __nv_bfloat16 lb = __float2bfloat16_rn(r);
    h = (uint32_t)*(uint16_t*)&hb;
    l = (uint32_t)*(uint16_t*)&lb;
}
__device__ __forceinline__ uint32_t bpack(uint32_t lo16, uint32_t hi16) {
    return lo16 | (hi16 << 16);
}

// ---------------------------------------------------------------------------
// bf16 smem geometry: A 128x16 bf16 rows (48B stride, conflict-free LDSM);
// B packed pairs [k/2][n] u32, 136-u32 row stride.
// ---------------------------------------------------------------------------
#define AROWB 48
#define ST_AB (128 * AROWB)             // 6144 B
#define BSTRU 136
#define ST_BB (8 * BSTRU * 4)           // 4352 B
#define STAGE_B (2 * ST_AB + 2 * ST_BB) // 20992 B
#define SMEM_GEMM (2 * STAGE_B)         // 41984 B
// stage layout: Ah @0, Al @ST_AB, Bh @2*ST_AB, Bl @2*ST_AB+ST_BB

// bf16 LDSM lane offset (bytes)
__device__ __forceinline__ int ldsm_lane_off_bf(int lane) {
    int row = (((lane >> 3) & 1) << 3) + (lane & 7);
    int colB = (lane >> 4) << 4;
    return row * AROWB + colB;
}

// ---------------------------------------------------------------------------
// 3xBF16 compute on a converted 128x16 stage: 8 ldsm + 16 LDS + 48 MMA / warp.
// ---------------------------------------------------------------------------
__device__ __forceinline__ void compute_stage_bf(
    uint32_t AhU, uint32_t AlU,
    const uint32_t* __restrict__ Bhp, const uint32_t* __restrict__ Blp,
    int warp_n, int gr, int tg, float acc[4][4][4])
{
    uint32_t bh[4][2], bl[4][2];
#pragma unroll
    for (int nt = 0; nt < 4; nt++) {
        int c = warp_n + nt * 8 + gr;
        bh[nt][0] = Bhp[tg * BSTRU + c];
        bh[nt][1] = Bhp[(tg + 4) * BSTRU + c];
        bl[nt][0] = Blp[tg * BSTRU + c];
        bl[nt][1] = Blp[(tg + 4) * BSTRU + c];
    }
#pragma unroll
    for (int mt = 0; mt < 4; mt++) {
        uint32_t ah[4], al[4];
        const uint32_t off = (uint32_t)(mt * 16 * AROWB);
        ldsm4(ah, AhU + off);
        ldsm4(al, AlU + off);
#pragma unroll
        for (int nt = 0; nt < 4; nt++) {
            mma_bf16(acc[mt][nt], ah, bh[nt]);
            mma_bf16(acc[mt][nt], ah, bl[nt]);
            mma_bf16(acc[mt][nt], al, bh[nt]);
        }
    }
}

// ---------------------------------------------------------------------------
// MLP GEMM (3xBF16): relu(A[M,1024] @ W[1024,1024] + bias)
// FUSE=0: write result to C. FUSE=1: fold against w3 -> partial logits,
// write g_part[row][32][4]; no C write.
// Block tile 128x128, 256 thr, double-buffered, 2 CTAs/SM.
// ---------------------------------------------------------------------------
template<int FUSE>
__global__ __launch_bounds__(256, 2)
void gemm_mma3(const float* __restrict__ A, const float* __restrict__ W,
               const float* __restrict__ bias, float* __restrict__ C,
               const float* __restrict__ w3, float* __restrict__ part)
{
    extern __shared__ __align__(16) char sm[];
    __shared__ float w3s[128 * 4];

    const int tid  = threadIdx.x;
    const int lane = tid & 31;
    const int wid  = tid >> 5;
    const int m0   = blockIdx.y * 128;
    const int n0   = blockIdx.x * 128;
    const int warp_m = (wid & 1) * 64;
    const int warp_n = (wid >> 1) * 32;
    const int gr = lane >> 2;
    const int tg = lane & 3;
    const uint32_t AU0 = smem_u32(sm)
        + (uint32_t)(warp_m * AROWB + ldsm_lane_off_bf(lane));

    if (FUSE && tid < 128)
        *(float4*)&w3s[tid * 4] = *(const float4*)(w3 + (size_t)(n0 + tid) * 4);

    float acc[4][4][4];
#pragma unroll
    for (int mt = 0; mt < 4; mt++)
#pragma unroll
        for (int nt = 0; nt < 4; nt++)
#pragma unroll
            for (int r = 0; r < 4; r++) acc[mt][nt][r] = 0.f;

    const int a_m  = tid >> 2;
    const int a_ks = (tid & 3) << 2;
    const int b_k0 = (tid >> 5) << 1;     // 0,2,..,14
    const int b_n4 = (tid & 31) << 2;

    const float* Arow0 = A + (size_t)(m0 + a_m) * 1024 + a_ks;
    const float* Arow1 = A + (size_t)(m0 + a_m + 64) * 1024 + a_ks;
    const float* Brow0 = W + (size_t)b_k0 * 1024 + n0 + b_n4;
    const float* Brow1 = W + (size_t)(b_k0 + 1) * 1024 + n0 + b_n4;

    float4 ra0, ra1, rb0, rb1;

    auto load_chunk = [&](int ch) {
        const size_t ko = (size_t)ch * 16;
        ra0 = *(const float4*)(Arow0 + ko);
        ra1 = *(const float4*)(Arow1 + ko);
        rb0 = *(const float4*)(Brow0 + ko * 1024);
        rb1 = *(const float4*)(Brow1 + ko * 1024);
    };
    auto store_chunk = [&](int p) {
        char* st = sm + p * STAGE_B;
        {
            uint32_t h0, l0, h1, l1, h2, l2, h3, l3;
            split_bf(ra0.x, h0, l0); split_bf(ra0.y, h1, l1);
            split_bf(ra0.z, h2, l2); split_bf(ra0.w, h3, l3);
            uint2 hv = make_uint2(bpack(h0, h1), bpack(h2, h3));
            uint2 lv = make_uint2(bpack(l0, l1), bpack(l2, l3));
            int off = a_m * AROWB + a_ks * 2;
            *(uint2*)(st + off) = hv;
            *(uint2*)(st + ST_AB + off) = lv;

            split_bf(ra1.x, h0, l0); split_bf(ra1.y, h1, l1);
            split_bf(ra1.z, h2, l2); split_bf(ra1.w, h3, l3);
            hv = make_uint2(bpack(h0, h1), bpack(h2, h3));
            lv = make_uint2(bpack(l0, l1), bpack(l2, l3));
            off = (a_m + 64) * AROWB + a_ks * 2;
            *(uint2*)(st + off) = hv;
            *(uint2*)(st + ST_AB + off) = lv;
        }
        {
            uint32_t ha, la, hb, lb;
            uint4 hv, lv;
            split_bf(rb0.x, ha, la); split_bf(rb1.x, hb, lb);
            hv.x = bpack(ha, hb); lv.x = bpack(la, lb);
            split_bf(rb0.y, ha, la); split_bf(rb1.y, hb, lb);
            hv.y = bpack(ha, hb); lv.y = bpack(la, lb);
            split_bf(rb0.z, ha, la); split_bf(rb1.z, hb, lb);
            hv.z = bpack(ha, hb); lv.z = bpack(la, lb);
            split_bf(rb0.w, ha, la); split_bf(rb1.w, hb, lb);
            hv.w = bpack(ha, hb); lv.w = bpack(la, lb);
            int off = ((b_k0 >> 1) * BSTRU + b_n4) * 4;
            *(uint4*)(st + 2 * ST_AB + off) = hv;
            *(uint4*)(st + 2 * ST_AB + ST_BB + off) = lv;
        }
    };
    auto compute_chunk = [&](int p) {
        const char* st = sm + p * STAGE_B;
        compute_stage_bf(AU0 + (uint32_t)(p * STAGE_B),
                         AU0 + (uint32_t)(p * STAGE_B + ST_AB),
                         (const uint32_t*)(st + 2 * ST_AB),
                         (const uint32_t*)(st + 2 * ST_AB + ST_BB),
                         warp_n, gr, tg, acc);
    };

    load_chunk(0);
    store_chunk(0);
    __syncthreads();

    for (int ch = 1; ch <= 64; ch++) {
        if (ch < 64) load_chunk(ch);
        compute_chunk((ch - 1) & 1);
        if (ch < 64) store_chunk(ch & 1);
        __syncthreads();
    }

    // ---- epilogue
    if (!FUSE) {
#pragma unroll
        for (int mt = 0; mt < 4; mt++) {
            int row = m0 + warp_m + mt * 16 + gr;
#pragma unroll
            for (int nt = 0; nt < 4; nt++) {
                int col = n0 + warp_n + nt * 8 + tg * 2;
                float b0 = bias[col], b1 = bias[col + 1];
                float2 v0, v1;
                v0.x = fmaxf(acc[mt][nt][0] + b0, 0.f);
                v0.y = fmaxf(acc[mt][nt][1] + b1, 0.f);
                v1.x = fmaxf(acc[mt][nt][2] + b0, 0.f);
                v1.y = fmaxf(acc[mt][nt][3] + b1, 0.f);
                *(float2*)(C + (size_t)row * 1024 + col) = v0;
                *(float2*)(C + (size_t)(row + 8) * 1024 + col) = v1;
            }
        }
    } else {
        const int slot = blockIdx.x * 4 + (warp_n >> 5);   // 0..31
#pragma unroll
        for (int mt = 0; mt < 4; mt++) {
            float p0[4] = {0.f, 0.f, 0.f, 0.f};
            float p1[4] = {0.f, 0.f, 0.f, 0.f};
#pragma unroll
            for (int nt = 0; nt < 4; nt++) {
                int lc  = warp_n + nt * 8 + tg * 2;       // local col
                int col = n0 + lc;
                float b0 = bias[col], b1 = bias[col + 1];
                float v00 = fmaxf(acc[mt][nt][0] + b0, 0.f);
                float v01 = fmaxf(acc[mt][nt][1] + b1, 0.f);
                float v10 = fmaxf(acc[mt][nt][2] + b0, 0.f);
                float v11 = fmaxf(acc[mt][nt][3] + b1, 0.f);
                const float* wc0 = &w3s[lc * 4];
                const float* wc1 = &w3s[(lc + 1) * 4];
#pragma unroll
                for (int c = 0; c < 4; c++) {
                    p0[c] += v00 * wc0[c] + v01 * wc1[c];
                    p1[c] += v10 * wc0[c] + v11 * wc1[c];
                }
            }
            // reduce over tg (lanes 4g..4g+3)
#pragma unroll
            for (int off = 1; off < 4; off <<= 1)
#pragma unroll
                for (int c = 0; c < 4; c++) {
                    p0[c] += __shfl_xor_sync(0xffffffffu, p0[c], off);
                    p1[c] += __shfl_xor_sync(0xffffffffu, p1[c], off);
                }
            if (tg == 0) {
                int row = m0 + warp_m + mt * 16 + gr;
                *(float4*)(part + ((size_t)row * 32 + slot) * 4) =
                    make_float4(p0[0], p0[1], p0[2], p0[3]);
                *(float4*)(part + ((size_t)(row + 8) * 32 + slot) * 4) =
                    make_float4(p1[0], p1[1], p1[2], p1[3]);
            }
        }
    }
}

// ---------------------------------------------------------------------------
// fc1 GEMM (3xBF16): x[b][hw][o] = feature[b][:][hw] . fc1_w[o][:] + fc1_b[o]
// A K-major gather (scalar LDG); B = g_wfc1T [k][128]. K=256 (16 chunks).
// ---------------------------------------------------------------------------
__global__ __launch_bounds__(256, 2)
void gemm_fc1(const float* __restrict__ feature, const float* __restrict__ Wt,
              const float* __restrict__ bias, float* __restrict__ X)
{
    extern __shared__ __align__(16) char sm[];

    const int tid  = threadIdx.x;
    const int lane = tid & 31;
    const int wid  = tid >> 5;
    const int b    = blockIdx.z;
    const int m0   = blockIdx.y * 128;
    const int warp_m = (wid & 1) * 64;
    const int warp_n = (wid >> 1) * 32;
    const int gr = lane >> 2;
    const int tg = lane & 3;
    const uint32_t AU0 = smem_u32(sm)
        + (uint32_t)(warp_m * AROWB + ldsm_lane_off_bf(lane));

    const float* Ab = feature + (size_t)b * C_IN * HW;
    float* Cb = X + (size_t)b * HW * DIM_LOI;

    float acc[4][4][4];
#pragma unroll
    for (int mt = 0; mt < 4; mt++)
#pragma unroll
        for (int nt = 0; nt < 4; nt++)
#pragma unroll
            for (int r = 0; r < 4; r++) acc[mt][nt][r] = 0.f;

    const int a_m  = tid & 127;
    const int a_kh = (tid >> 7) << 3;
    const int b_k0 = (tid >> 5) << 1;
    const int b_n4 = (tid & 31) << 2;

    const float* Acol = Ab + (size_t)a_kh * HW + m0 + a_m;
    const float* Brow0 = Wt + (size_t)b_k0 * 128 + b_n4;
    const float* Brow1 = Wt + (size_t)(b_k0 + 1) * 128 + b_n4;

    float ra[8];
    float4 rb0, rb1;

    auto load_chunk = [&](int ch) {
        const size_t ko = (size_t)ch * 16;
#pragma unroll
        for (int j = 0; j < 8; j++)
            ra[j] = Acol[(ko + j) * HW];
        rb0 = *(const float4*)(Brow0 + ko * 128);
        rb1 = *(const float4*)(Brow1 + ko * 128);
    };
    auto store_chunk = [&](int p) {
        char* st = sm + p * STAGE_B;
        {
            uint32_t h[8], l[8];
#pragma unroll
            for (int j = 0; j < 8; j++) split_bf(ra[j], h[j], l[j]);
            uint4 hv = make_uint4(bpack(h[0], h[1]), bpack(h[2], h[3]),
                                  bpack(h[4], h[5]), bpack(h[6], h[7]));
            uint4 lv = make_uint4(bpack(l[0], l[1]), bpack(l[2], l[3]),
                                  bpack(l[4], l[5]), bpack(l[6], l[7]));
            int off = a_m * AROWB + a_kh * 2;
            *(uint4*)(st + off) = hv;
            *(uint4*)(st + ST_AB + off) = lv;
        }
        {
            uint32_t ha, la, hb, lb;
            uint4 hv, lv;
            split_bf(rb0.x, ha, la); split_bf(rb1.x, hb, lb);
            hv.x = bpack(ha, hb); lv.x = bpack(la, lb);
            split_bf(rb0.y, ha, la); split_bf(rb1.y, hb, lb);
            hv.y = bpack(ha, hb); lv.y = bpack(la, lb);
            split_bf(rb0.z, ha, la); split_bf(rb1.z, hb, lb);
            hv.z = bpack(ha, hb); lv.z = bpack(la, lb);
            split_bf(rb0.w, ha, la); split_bf(rb1.w, hb, lb);
            hv.w = bpack(ha, hb); lv.w = bpack(la, lb);
            int off = ((b_k0 >> 1) * BSTRU + b_n4) * 4;
            *(uint4*)(st + 2 * ST_AB + off) = hv;
            *(uint4*)(st + 2 * ST_AB + ST_BB + off) = lv;
        }
    };
    auto compute_chunk = [&](int p) {
        const char* st = sm + p * STAGE_B;
        compute_stage_bf(AU0 + (uint32_t)(p * STAGE_B),
                         AU0 + (uint32_t)(p * STAGE_B + ST_AB),
                         (const uint32_t*)(st + 2 * ST_AB),
                         (const uint32_t*)(st + 2 * ST_AB + ST_BB),
                         warp_n, gr, tg, acc);
    };

    load_chunk(0);
    store_chunk(0);
    __syncthreads();

    for (int ch = 1; ch <= 16; ch++) {
        if (ch < 16) load_chunk(ch);
        compute_chunk((ch - 1) & 1);
        if (ch < 16) store_chunk(ch & 1);
        __syncthreads();
    }

#pragma unroll
    for (int mt = 0; mt < 4; mt++) {
        int row = m0 + warp_m + mt * 16 + gr;
#pragma unroll
        for (int nt = 0; nt < 4; nt++) {
            int col = warp_n + nt * 8 + tg * 2;
            float b0 = bias[col], b1 = bias[col + 1];
            float2 v0, v1;
            v0.x = acc[mt][nt][0] + b0;
            v0.y = acc[mt][nt][1] + b1;
            v1.x = acc[mt][nt][2] + b0;
            v1.y = acc[mt][nt][3] + b1;
            *(float2*)(Cb + (size_t)row * 128 + col) = v0;
            *(float2*)(Cb + (size_t)(row + 8) * 128 + col) = v1;
        }
    }
}

// ---------------------------------------------------------------------------
// fc1_w [128][256] -> Wt [256][128]
// ---------------------------------------------------------------------------
__global__ __launch_bounds__(256)
void transpose_fc1(const float* __restrict__ s, float* __restrict__ d)
{
    __shared__ float t[32][33];
    const int bx = blockIdx.x * 32;   // k
    const int by = blockIdx.y * 32;   // n
    const int tx = threadIdx.x, ty = threadIdx.y;
#pragma unroll
    for (int r = 0; r < 32; r += 8)
        t[ty + r][tx] = s[(size_t)(by + ty + r) * 256 + bx + tx];
    __syncthreads();
#pragma unroll
    for (int r = 0; r < 32; r += 8)
        d[(size_t)(bx + ty + r) * 128 + by + tx] = t[tx][ty + r];
}

// ---------------------------------------------------------------------------
// Bilinear sampling + maxpool. One block per line, thread = channel.
// ---------------------------------------------------------------------------
__global__ __launch_bounds__(128)
void sample_kernel(const float* __restrict__ lines, float* __restrict__ feat)
{
    const int bl = blockIdx.x;
    const int b  = bl / LL;
    const int c  = threadIdx.x;

    const float* xb = g_x + (size_t)b * HW * DIM_LOI;

    float4 ln = *(const float4*)(lines + (size_t)bl * 4);
    const float x0 = ln.x, y0 = ln.y, x1 = ln.z, y1 = ln.w;

    __shared__ float stage[DIM_LOI * N_PTS1];

    float maxv = 0.f;
#pragma unroll 4
    for (int pt = 0; pt < N_PTS0; pt++) {
        float lam = (float)pt * (1.0f / 31.0f);
        float px = x0 * lam + x1 * (1.0f - lam) - 0.5f;
        float py = y0 * lam + y1 * (1.0f - lam) - 0.5f;

        float px0 = fminf(fmaxf(floorf(px), 0.f), (float)(HH - 1));
        float py0 = fminf(fmaxf(floorf(py), 0.f), (float)(WW - 1));
        float px1 = fminf(px0 + 1.f, (float)(HH - 1));
        float py1 = fminf(py0 + 1.f, (float)(WW - 1));
        int ix0 = (int)px0, iy0 = (int)py0, ix1 = (int)px1, iy1 = (int)py1;

        float w00 = (px1 - px) * (py1 - py);
        float w10 = (px - px0) * (py1 - py);
        float w01 = (px1 - px) * (py - py0);
        float w11 = (px - px0) * (py - py0);

        const float* t00 = xb + (size_t)(ix0 * WW + iy0) * DIM_LOI + c;
        const float* t10 = xb + (size_t)(ix1 * WW + iy0) * DIM_LOI + c;
        const float* t01 = xb + (size_t)(ix0 * WW + iy1) * DIM_LOI + c;
        const float* t11 = xb + (size_t)(ix1 * WW + iy1) * DIM_LOI + c;
        float v = w00 * (*t00) + w10 * (*t10) + w01 * (*t01) + w11 * (*t11);

        if ((pt & 3) == 0) maxv = v; else maxv = fmaxf(maxv, v);
        if ((pt & 3) == 3) stage[c * N_PTS1 + (pt >> 2)] = maxv;
    }
    __syncthreads();

    float* frow = feat + (size_t)bl * DIM_FC;
    for (int i = c; i < DIM_FC; i += DIM_LOI) frow[i] = stage[i];
}

// ---------------------------------------------------------------------------
// Reduce partial logits (32 slots) -> softmax + keep/key. Warp per row.
// ---------------------------------------------------------------------------
__global__ __launch_bounds__(256)
void reduce_softmax(const float* __restrict__ part, const float* __restrict__ b3)
{
    const int w    = threadIdx.x >> 5;
    const int lane = threadIdx.x & 31;
    const int row  = blockIdx.x * 8 + w;
    if (row >= NROWS) return;

    float4 p = *(const float4*)(part + ((size_t)row * 32 + lane) * 4);
    float a0 = p.x, a1 = p.y, a2 = p.z, a3 = p.w;
#pragma unroll
    for (int off = 16; off; off >>= 1) {
        a0 += __shfl_down_sync(0xffffffffu, a0, off);
        a1 += __shfl_down_sync(0xffffffffu, a1, off);
        a2 += __shfl_down_sync(0xffffffffu, a2, off);
        a3 += __shfl_down_sync(0xffffffffu, a3, off);
    }
    if (lane == 0) {
        float lg[4] = {a0 + b3[0], a1 + b3[1], a2 + b3[2], a3 + b3[3]};
        float mx = fmaxf(fmaxf(lg[0], lg[1]), fmaxf(lg[2], lg[3]));
        float e[4], sum = 0.f;
#pragma unroll
        for (int n = 0; n < 4; n++) { e[n] = __expf(lg[n] - mx); sum += e[n]; }
        float inv = 1.0f / sum;
        float s0 = e[0] * inv, s1 = e[1] * inv, s2 = e[2] * inv, s3 = e[3] * inv;
        *(float4*)(g_s + (size_t)row * 4) = make_float4(s0, s1, s2, s3);

        bool keep = ((s1 > 0.25f) || (s2 > 0.25f) || (s3 > 0.25f)) && (s0 < 0.25f);
        int am = 0; float best = s0;
        if (s1 > best) { best = s1; am = 1; }
        if (s2 > best) { best = s2; am = 2; }
        if (s3 > best) { best = s3; am = 3; }
        g_key[row] = keep ? am : -1;
    }
}

// ---------------------------------------------------------------------------
// Stable counting sort by key desc (buckets 3,2,1). One block per batch.
// ---------------------------------------------------------------------------
__global__ __launch_bounds__(1024)
void select_kernel()
{
    const int b = blockIdx.x;
    const int t = threadIdx.x;
    const int* key = g_key + b * LL;

    __shared__ int sc[3][1024];

    const int l0 = t * 5;
    const int l1 = min(l0 + 5, LL);
    int n1 = 0, n2 = 0, n3 = 0;
    for (int i = l0; i < l1; i++) {
        int k = key[i];
        n1 += (k == 1); n2 += (k == 2); n3 += (k == 3);
    }
    sc[0][t] = n1; sc[1][t] = n2; sc[2][t] = n3;
    __syncthreads();

    for (int off = 1; off < 1024; off <<= 1) {
        int v0 = (t >= off) ? sc[0][t - off] : 0;
        int v1 = (t >= off) ? sc[1][t - off] : 0;
        int v2 = (t >= off) ? sc[2][t - off] : 0;
        __syncthreads();
        sc[0][t] += v0; sc[1][t] += v1; sc[2][t] += v2;
        __syncthreads();
    }

    const int T1 = sc[0][1023], T2 = sc[1][1023], T3 = sc[2][1023];
    int p3 = sc[2][t] - n3;
    int p2 = T3 + (sc[1][t] - n2);
    int p1 = T3 + T2 + (sc[0][t] - n1);

    int* ord = g_order + b * LL;
    for (int i = l0; i < l1; i++) {
        int k = key[i];
        if (k == 3)      ord[p3++] = i;
        else if (k == 2) ord[p2++] = i;
        else if (k == 1) ord[p1++] = i;
    }
    if (t == 0) g_cnt[b] = T1 + T2 + T3;
}

// ---------------------------------------------------------------------------
// Output writer
// ---------------------------------------------------------------------------
__global__ void out_writer(const float* __restrict__ lines,
                           float* __restrict__ out, int out_size)
{
    const int gid = blockIdx.x * blockDim.x + threadIdx.x;

    if (gid < BB * N_OUT) {
        int b = gid / N_OUT, r = gid - b * N_OUT;
        int cnt = g_cnt[b];
        float4 lo = {0.f, 0.f, 0.f, 0.f};
        float4 so = {0.f, 0.f, 0.f, 0.f};
        if (cnt > 0) {
            int idx = g_order[b * LL + (r % cnt)];
            lo = *(const float4*)(lines + (size_t)(b * LL + idx) * 4);
            so = *(const float4*)(g_s + (size_t)(b * LL + idx) * 4);
        }
        *(float4*)(out + (size_t)gid * 4) = lo;
        if (out_size >= 2 * 4 * BB * N_OUT)
            *(float4*)(out + (size_t)(BB * N_OUT + gid) * 4) = so;
    }
    int g2 = gid - BB * N_OUT;
    if (g2 >= 0 && g2 < NROWS && out_size >= 8 * BB * N_OUT + 4 * NROWS) {
        *(float4*)(out + (size_t)(2 * BB * N_OUT + g2) * 4) =
            *(const float4*)(g_s + (size_t)g2 * 4);
    }
}

// ---------------------------------------------------------------------------
// Launch
// ---------------------------------------------------------------------------
extern "C" void kernel_launch(void* const* d_in, const int* in_sizes, int n_in,
                              void* d_out, int out_size)
{
    const float* feature = (const float*)d_in[0];
    const float* lines   = (const float*)d_in[1];
    const float* fc1_w   = (const float*)d_in[2];
    const float* fc1_b   = (const float*)d_in[3];
    const float* w1      = (const float*)d_in[4];
    const float* b1      = (const float*)d_in[5];
    const float* w2      = (const float*)d_in[6];
    const float* b2      = (const float*)d_in[7];
    const float* w3      = (const float*)d_in[8];
    const float* b3      = (const float*)d_in[9];
    float* out = (float*)d_out;

    float *x_p, *feat_p, *h1_p, *part_p, *wt_p;
    cudaGetSymbolAddress((void**)&x_p,    g_x);
    cudaGetSymbolAddress((void**)&feat_p, g_feat);
    cudaGetSymbolAddress((void**)&h1_p,   g_h1);
    cudaGetSymbolAddress((void**)&part_p, g_part);
    cudaGetSymbolAddress((void**)&wt_p,   g_wfc1T);

    cudaFuncSetAttribute(gemm_mma3<0>, cudaFuncAttributeMaxDynamicSharedMemorySize,
                         SMEM_GEMM);
    cudaFuncSetAttribute(gemm_mma3<1>, cudaFuncAttributeMaxDynamicSharedMemorySize,
                         SMEM_GEMM);
    cudaFuncSetAttribute(gemm_fc1, cudaFuncAttributeMaxDynamicSharedMemorySize,
                         SMEM_GEMM);

    // fc1_w -> [k][n]
    transpose_fc1<<<dim3(8, 4), dim3(32, 8)>>>(fc1_w, wt_p);

    // fc1 on tensor cores (3xBF16)
    gemm_fc1<<<dim3(1, HW / 128, BB), 256, SMEM_GEMM>>>(feature, wt_p, fc1_b, x_p);

    // bilinear sample + maxpool -> feat
    sample_kernel<<<NROWS, DIM_LOI>>>(lines, feat_p);

    // MLP layer 1 (3xBF16)
    gemm_mma3<0><<<dim3(8, NPAD / 128), 256, SMEM_GEMM>>>(
        feat_p, w1, b1, h1_p, nullptr, nullptr);
    // MLP layer 2 fused with w3 partial logits
    gemm_mma3<1><<<dim3(8, NPAD / 128), 256, SMEM_GEMM>>>(
        h1_p, w2, b2, nullptr, w3, part_p);

    // reduce partials -> softmax + keep/key
    reduce_softmax<<<(NROWS + 7) / 8, 256>>>(part_p, b3);

    // stable bucket sort per batch
    select_kernel<<<BB, 1024>>>();

    // outputs
    int tot = BB * N_OUT + NROWS;
    out_writer<<<(tot + 255) / 256, 256>>>(lines, out, out_size);
}